// round 3
// baseline (speedup 1.0000x reference)
#include <cuda_runtime.h>
#include <cuda_bf16.h>
#include <math.h>

// Problem constants
#define BATCH 2
#define CH    64          // feature channels = first-layer inputs (plus time)
#define HGT   192
#define WID   320
#define HW    (HGT*WID)   // 61440
#define ROWS_PER_TIME (BATCH*HW)   // 122880
#define NTIMES 3
#define OUTC  64

#define TILE_ROWS 64
#define THREADS   256
#define STRIDE    260     // smem row stride (floats): multiple of 4 (float4), not mult of 32*? avoids worst conflicts

#define W0S 30.0f

// ---------------------------------------------------------------------------
// Generic dense layer: out[r][j] = act( sum_k in[r][k]*W[j][k] + b[j] )
// 64 rows per block, N outputs processed in chunks of 64 columns.
// Thread (ty,tx) with ty=tid/16, tx=tid%16 computes rows r0..r0+3 (r0=4*ty)
// and cols jc..jc+3 (jc = chunk*64 + 4*tx).
// ---------------------------------------------------------------------------
template<int K, int N, bool SIN>
__device__ __forceinline__ void layer(const float* __restrict__ W,
                                      const float* __restrict__ bias,
                                      const float* __restrict__ in_sh,
                                      float* __restrict__ out_sh,
                                      int tid)
{
    const int ty = tid >> 4;
    const int tx = tid & 15;
    const int r0 = ty << 2;

#pragma unroll
    for (int chunk = 0; chunk < N / 64; ++chunk) {
        const int jc = chunk * 64 + (tx << 2);
        float acc[4][4];
#pragma unroll
        for (int jj = 0; jj < 4; ++jj) {
            const float bv = __ldg(&bias[jc + jj]);
#pragma unroll
            for (int i = 0; i < 4; ++i) acc[i][jj] = bv;
        }

#pragma unroll 4
        for (int k = 0; k < K; k += 4) {
            float4 xv[4];
            float4 wv[4];
#pragma unroll
            for (int i = 0; i < 4; ++i)
                xv[i] = *reinterpret_cast<const float4*>(&in_sh[(r0 + i) * STRIDE + k]);
#pragma unroll
            for (int jj = 0; jj < 4; ++jj)
                wv[jj] = __ldg(reinterpret_cast<const float4*>(&W[(size_t)(jc + jj) * K + k]));
#pragma unroll
            for (int i = 0; i < 4; ++i) {
#pragma unroll
                for (int jj = 0; jj < 4; ++jj) {
                    acc[i][jj] = fmaf(xv[i].x, wv[jj].x, acc[i][jj]);
                    acc[i][jj] = fmaf(xv[i].y, wv[jj].y, acc[i][jj]);
                    acc[i][jj] = fmaf(xv[i].z, wv[jj].z, acc[i][jj]);
                    acc[i][jj] = fmaf(xv[i].w, wv[jj].w, acc[i][jj]);
                }
            }
        }

#pragma unroll
        for (int i = 0; i < 4; ++i) {
            float4 o;
            if (SIN) {
                o.x = sinf(W0S * acc[i][0]);
                o.y = sinf(W0S * acc[i][1]);
                o.z = sinf(W0S * acc[i][2]);
                o.w = sinf(W0S * acc[i][3]);
            } else {
                o.x = acc[i][0]; o.y = acc[i][1]; o.z = acc[i][2]; o.w = acc[i][3];
            }
            *reinterpret_cast<float4*>(&out_sh[(r0 + i) * STRIDE + jc]) = o;
        }
    }
}

// ---------------------------------------------------------------------------
// Layer 0: K = 65 (64 features + time scalar). Row stride 65 is not
// 16B-aligned, so use scalar weight loads; the time term folds into the
// accumulator init: acc = b0[j] + t * W0[j][64].
// ---------------------------------------------------------------------------
__device__ __forceinline__ void layer0(const float* __restrict__ W,
                                       const float* __restrict__ bias,
                                       float tval,
                                       const float* __restrict__ in_sh,
                                       float* __restrict__ out_sh,
                                       int tid)
{
    const int ty = tid >> 4;
    const int tx = tid & 15;
    const int r0 = ty << 2;
    const int jc = tx << 2;

    float acc[4][4];
#pragma unroll
    for (int jj = 0; jj < 4; ++jj) {
        const float bv = __ldg(&bias[jc + jj]) + tval * __ldg(&W[(jc + jj) * 65 + 64]);
#pragma unroll
        for (int i = 0; i < 4; ++i) acc[i][jj] = bv;
    }

#pragma unroll 4
    for (int k = 0; k < 64; ++k) {
        float xs[4];
#pragma unroll
        for (int i = 0; i < 4; ++i) xs[i] = in_sh[(r0 + i) * STRIDE + k];
#pragma unroll
        for (int jj = 0; jj < 4; ++jj) {
            const float wv = __ldg(&W[(jc + jj) * 65 + k]);
#pragma unroll
            for (int i = 0; i < 4; ++i) acc[i][jj] = fmaf(xs[i], wv, acc[i][jj]);
        }
    }

#pragma unroll
    for (int i = 0; i < 4; ++i) {
        float4 o;
        o.x = sinf(W0S * acc[i][0]);
        o.y = sinf(W0S * acc[i][1]);
        o.z = sinf(W0S * acc[i][2]);
        o.w = sinf(W0S * acc[i][3]);
        *reinterpret_cast<float4*>(&out_sh[(r0 + i) * STRIDE + jc]) = o;
    }
}

// ---------------------------------------------------------------------------
// Fused SIREN MLP kernel: one CTA = 64 rows (one contiguous pixel span of
// one (time, batch) pair), full 6-layer MLP with smem ping-pong activations.
// ---------------------------------------------------------------------------
extern "C" __global__ void __launch_bounds__(THREADS, 1)
liif_siren_kernel(const float* __restrict__ feat,
                  const float* __restrict__ times,
                  const float* __restrict__ w0, const float* __restrict__ b0,
                  const float* __restrict__ w1, const float* __restrict__ b1,
                  const float* __restrict__ w2, const float* __restrict__ b2,
                  const float* __restrict__ w3, const float* __restrict__ b3,
                  const float* __restrict__ w4, const float* __restrict__ b4,
                  const float* __restrict__ w5, const float* __restrict__ b5,
                  float* __restrict__ out)
{
    extern __shared__ float sm[];
    float* bufA = sm;                       // 64 * STRIDE floats
    float* bufB = sm + TILE_ROWS * STRIDE;  // 64 * STRIDE floats

    const int tid = threadIdx.x;
    const int g0  = blockIdx.x * TILE_ROWS;       // global row of first tile row
    const int c   = g0 / ROWS_PER_TIME;           // time index 0..2
    const int rem = g0 - c * ROWS_PER_TIME;
    const int b   = rem / HW;                     // batch index
    const int p0  = rem - b * HW;                 // pixel offset (64-aligned)

    const float tval = __ldg(&times[c]);

    // ---- load input tile: bufA[r][k] = feat[b][k][p0 + r], k < 64 ----
    const float* fbase = feat + ((size_t)b * CH) * HW + p0;
    for (int idx = tid; idx < CH * (TILE_ROWS / 4); idx += THREADS) {
        const int k  = idx >> 4;         // 0..63
        const int rq = idx & 15;         // 0..15 (groups of 4 rows)
        const float4 v = __ldg(reinterpret_cast<const float4*>(&fbase[(size_t)k * HW + rq * 4]));
        const int r = rq << 2;
        bufA[(r + 0) * STRIDE + k] = v.x;
        bufA[(r + 1) * STRIDE + k] = v.y;
        bufA[(r + 2) * STRIDE + k] = v.z;
        bufA[(r + 3) * STRIDE + k] = v.w;
    }
    __syncthreads();

    // ---- MLP chain ----
    layer0(w0, b0, tval, bufA, bufB, tid);      __syncthreads();
    layer<64, 64, true >(w1, b1, bufB, bufA, tid); __syncthreads();
    layer<64, 256, true >(w2, b2, bufA, bufB, tid); __syncthreads();
    layer<256, 256, true >(w3, b3, bufB, bufA, tid); __syncthreads();
    layer<256, 256, true >(w4, b4, bufA, bufB, tid); __syncthreads();
    layer<256, 64, false>(w5, b5, bufB, bufA, tid); __syncthreads();

    // ---- write output: out[c][b][j][p0 + r] = bufA[r][j] ----
    float* obase = out + ((size_t)(c * BATCH + b) * OUTC) * HW + p0;
    for (int idx = tid; idx < OUTC * (TILE_ROWS / 4); idx += THREADS) {
        const int j  = idx >> 4;         // 0..63
        const int rq = idx & 15;
        const int r  = rq << 2;
        float4 v;
        v.x = bufA[(r + 0) * STRIDE + j];
        v.y = bufA[(r + 1) * STRIDE + j];
        v.z = bufA[(r + 2) * STRIDE + j];
        v.w = bufA[(r + 3) * STRIDE + j];
        *reinterpret_cast<float4*>(&obase[(size_t)j * HW + rq * 4]) = v;
    }
}

extern "C" void kernel_launch(void* const* d_in, const int* in_sizes, int n_in,
                              void* d_out, int out_size)
{
    const float* feat  = (const float*)d_in[0];
    const float* times = (const float*)d_in[1];
    const float* w0 = (const float*)d_in[2];  const float* b0 = (const float*)d_in[3];
    const float* w1 = (const float*)d_in[4];  const float* b1 = (const float*)d_in[5];
    const float* w2 = (const float*)d_in[6];  const float* b2 = (const float*)d_in[7];
    const float* w3 = (const float*)d_in[8];  const float* b3 = (const float*)d_in[9];
    const float* w4 = (const float*)d_in[10]; const float* b4 = (const float*)d_in[11];
    const float* w5 = (const float*)d_in[12]; const float* b5 = (const float*)d_in[13];
    float* out = (float*)d_out;

    const size_t smem_bytes = 2 * TILE_ROWS * STRIDE * sizeof(float); // 133120
    cudaFuncSetAttribute(liif_siren_kernel,
                         cudaFuncAttributeMaxDynamicSharedMemorySize,
                         (int)smem_bytes);

    const int total_rows = NTIMES * ROWS_PER_TIME;   // 368640
    const int blocks = total_rows / TILE_ROWS;       // 5760

    liif_siren_kernel<<<blocks, THREADS, smem_bytes>>>(
        feat, times,
        w0, b0, w1, b1, w2, b2, w3, b3, w4, b4, w5, b5,
        out);
}

// round 5
// speedup vs baseline: 4.6206x; 4.6206x over previous
#include <cuda_runtime.h>
#include <cuda_bf16.h>
#include <math.h>
#include <stdint.h>

// Problem constants
#define BATCH 2
#define CH    64
#define HGT   192
#define WID   320
#define HW    (HGT*WID)            // 61440
#define ROWS_PER_TIME (BATCH*HW)   // 122880
#define NTIMES 3
#define OUTC  64

#define TILE_ROWS 64
#define THREADS   256
#define W0S 30.0f

// Shared memory layout (bytes). Activation buffers are [k][r] transposed,
// 256 rows (max K) x 64 cols, row = 256B. Weight buffer: [64 j][K k], K<=256.
#define SM_A   0u
#define SM_B   65536u
#define SM_W   131072u
#define SM_WT  196608u            // 64 floats (layer-0 time column)
#define SM_TOTAL 196864u

// XOR swizzle: permute 16B blocks within each 128B region by (row>>2)&7.
__device__ __forceinline__ uint32_t swz(uint32_t row_idx) {
    return (row_idx >> 2 & 7u) << 4;
}

// ---- packed f32x2 helpers -------------------------------------------------
__device__ __forceinline__ unsigned long long pk(float lo, float hi) {
    unsigned long long r;
    asm("mov.b64 %0, {%1, %2};" : "=l"(r)
        : "r"(__float_as_uint(lo)), "r"(__float_as_uint(hi)));
    return r;
}
__device__ __forceinline__ void unpk(unsigned long long v, float& lo, float& hi) {
    uint32_t a, b;
    asm("mov.b64 {%0, %1}, %2;" : "=r"(a), "=r"(b) : "l"(v));
    lo = __uint_as_float(a); hi = __uint_as_float(b);
}
__device__ __forceinline__ unsigned long long fma2(unsigned long long a,
                                                   unsigned long long b,
                                                   unsigned long long c) {
    unsigned long long d;
    asm("fma.rn.f32x2 %0, %1, %2, %3;" : "=l"(d) : "l"(a), "l"(b), "l"(c));
    return d;
}

// ---- weight staging: 64 rows x K floats, coalesced LDG -> swizzled STS ----
template<int K>
__device__ __forceinline__ void stage_w(const float* __restrict__ Wg, int jc0,
                                        char* __restrict__ wbuf, int tid)
{
    const int nf4 = 64 * K / 4;
#pragma unroll 4
    for (int idx = tid; idx < nf4; idx += THREADS) {
        const int j  = idx / (K / 4);
        const int kq = idx - j * (K / 4);
        const float4 v = __ldg(reinterpret_cast<const float4*>(
            &Wg[(size_t)(jc0 + j) * K + kq * 4]));
        *reinterpret_cast<float4*>(
            wbuf + (((uint32_t)(j * K + kq * 4) * 4u) ^ swz((uint32_t)j))) = v;
    }
}

// ---- fused dense chunk: 64 rows x 64 cols, K inputs, packed f32x2 ---------
// in buffer [k][r] swizzled, weights [j_local][k] swizzled, out [j][r] swizzled.
template<int K, bool SIN, bool HASWT>
__device__ __forceinline__ void compute_chunk(
    const char* __restrict__ wbuf, const float* __restrict__ bias,
    const float* __restrict__ wt, float tval,
    const char* __restrict__ inbuf, char* __restrict__ outbuf,
    int jc0, int tid)
{
    const int tx = tid & 15;
    const int ty = tid >> 4;
    const int r0 = ty << 2;
    const uint32_t swzw = (uint32_t)(tx & 7) << 4;

    unsigned long long acc[2][4];
#pragma unroll
    for (int jj = 0; jj < 4; ++jj) {
        const int jl = (tx << 2) + jj;
        float bv = __ldg(&bias[jc0 + jl]);
        if (HASWT) bv += tval * wt[jl];
        const unsigned long long p = pk(bv, bv);
        acc[0][jj] = p; acc[1][jj] = p;
    }

#pragma unroll 2
    for (int k = 0; k < K; k += 4) {
        const uint32_t aswz = swz((uint32_t)k);     // constant for kk=0..3
        float4 xv[4];
#pragma unroll
        for (int kk = 0; kk < 4; ++kk)
            xv[kk] = *reinterpret_cast<const float4*>(
                inbuf + (((uint32_t)((k + kk) * 64 + r0) * 4u) ^ aswz));
        float4 wv[4];
#pragma unroll
        for (int jj = 0; jj < 4; ++jj)
            wv[jj] = *reinterpret_cast<const float4*>(
                wbuf + (((uint32_t)(((tx << 2) + jj) * K + k) * 4u) ^ swzw));
#pragma unroll
        for (int kk = 0; kk < 4; ++kk) {
            const unsigned long long a01 = pk(xv[kk].x, xv[kk].y);
            const unsigned long long a23 = pk(xv[kk].z, xv[kk].w);
#pragma unroll
            for (int jj = 0; jj < 4; ++jj) {
                const float w = (kk == 0) ? wv[jj].x :
                                (kk == 1) ? wv[jj].y :
                                (kk == 2) ? wv[jj].z : wv[jj].w;
                const unsigned long long wd = pk(w, w);
                acc[0][jj] = fma2(a01, wd, acc[0][jj]);
                acc[1][jj] = fma2(a23, wd, acc[1][jj]);
            }
        }
    }

#pragma unroll
    for (int jj = 0; jj < 4; ++jj) {
        const int jg = jc0 + (tx << 2) + jj;
        float f0, f1, f2, f3;
        unpk(acc[0][jj], f0, f1);
        unpk(acc[1][jj], f2, f3);
        float4 o;
        if (SIN) {
            o.x = __sinf(W0S * f0); o.y = __sinf(W0S * f1);
            o.z = __sinf(W0S * f2); o.w = __sinf(W0S * f3);
        } else {
            o.x = f0; o.y = f1; o.z = f2; o.w = f3;
        }
        *reinterpret_cast<float4*>(
            outbuf + (((uint32_t)(jg * 64 + r0) * 4u) ^ swz((uint32_t)jg))) = o;
    }
}

// ---------------------------------------------------------------------------
extern "C" __global__ void __launch_bounds__(THREADS, 1)
liif_siren_kernel(const float* __restrict__ feat,
                  const float* __restrict__ times,
                  const float* __restrict__ w0, const float* __restrict__ b0,
                  const float* __restrict__ w1, const float* __restrict__ b1,
                  const float* __restrict__ w2, const float* __restrict__ b2,
                  const float* __restrict__ w3, const float* __restrict__ b3,
                  const float* __restrict__ w4, const float* __restrict__ b4,
                  const float* __restrict__ w5, const float* __restrict__ b5,
                  float* __restrict__ out)
{
    extern __shared__ char smb[];
    char* bufA = smb + SM_A;
    char* bufB = smb + SM_B;
    char* wbuf = smb + SM_W;
    float* wt  = reinterpret_cast<float*>(smb + SM_WT);

    const int tid = threadIdx.x;
    const int g0  = blockIdx.x * TILE_ROWS;
    const int c   = g0 / ROWS_PER_TIME;
    const int rem = g0 - c * ROWS_PER_TIME;
    const int b   = rem / HW;
    const int p0  = rem - b * HW;

    const float tval = __ldg(&times[c]);

    // ---- stage input tile: bufA[k][r] = feat[b][k][p0+r] (coalesced) ----
    const float* fbase = feat + ((size_t)b * CH) * HW + p0;
#pragma unroll 4
    for (int idx = tid; idx < CH * (TILE_ROWS / 4); idx += THREADS) {
        const int k  = idx >> 4;
        const int rq = idx & 15;
        const float4 v = __ldg(reinterpret_cast<const float4*>(
            &fbase[(size_t)k * HW + rq * 4]));
        *reinterpret_cast<float4*>(
            bufA + (((uint32_t)(k * 64 + rq * 4) * 4u) ^ swz((uint32_t)k))) = v;
    }

    // ---- stage layer-0 weights: 64x64 (cols 0..63) + time column wt[j] ----
    for (int idx = tid; idx < 64 * 64; idx += THREADS) {
        const int j = idx >> 6;
        const int k = idx & 63;
        const float v = __ldg(&w0[j * 65 + k]);
        *reinterpret_cast<float*>(
            wbuf + (((uint32_t)(j * 64 + k) * 4u) ^ swz((uint32_t)j))) = v;
    }
    if (tid < 64) wt[tid] = __ldg(&w0[tid * 65 + 64]);
    __syncthreads();

    // ---- layer 0: 65 -> 64 (time folded into bias) ----
    compute_chunk<64, true, true>(wbuf, b0, wt, tval, bufA, bufB, 0, tid);

    // ---- layer 1: 64 -> 64 ----
    __syncthreads();
    stage_w<64>(w1, 0, wbuf, tid);
    __syncthreads();
    compute_chunk<64, true, false>(wbuf, b1, nullptr, 0.f, bufB, bufA, 0, tid);

    // ---- layer 2: 64 -> 256 ----
#pragma unroll 1
    for (int jc0 = 0; jc0 < 256; jc0 += 64) {
        __syncthreads();
        stage_w<64>(w2, jc0, wbuf, tid);
        __syncthreads();
        compute_chunk<64, true, false>(wbuf, b2, nullptr, 0.f, bufA, bufB, jc0, tid);
    }

    // ---- layer 3: 256 -> 256 ----
#pragma unroll 1
    for (int jc0 = 0; jc0 < 256; jc0 += 64) {
        __syncthreads();
        stage_w<256>(w3, jc0, wbuf, tid);
        __syncthreads();
        compute_chunk<256, true, false>(wbuf, b3, nullptr, 0.f, bufB, bufA, jc0, tid);
    }

    // ---- layer 4: 256 -> 256 ----
#pragma unroll 1
    for (int jc0 = 0; jc0 < 256; jc0 += 64) {
        __syncthreads();
        stage_w<256>(w4, jc0, wbuf, tid);
        __syncthreads();
        compute_chunk<256, true, false>(wbuf, b4, nullptr, 0.f, bufA, bufB, jc0, tid);
    }

    // ---- layer 5: 256 -> 64, no activation ----
    __syncthreads();
    stage_w<256>(w5, 0, wbuf, tid);
    __syncthreads();
    compute_chunk<256, false, false>(wbuf, b5, nullptr, 0.f, bufB, bufA, 0, tid);
    __syncthreads();

    // ---- write output: out[c][b][j][p0+r] = bufA[j][r] (coalesced) ----
    float* obase = out + ((size_t)(c * BATCH + b) * OUTC) * HW + p0;
#pragma unroll 4
    for (int idx = tid; idx < OUTC * (TILE_ROWS / 4); idx += THREADS) {
        const int j  = idx >> 4;
        const int rq = idx & 15;
        const float4 v = *reinterpret_cast<const float4*>(
            bufA + (((uint32_t)(j * 64 + rq * 4) * 4u) ^ swz((uint32_t)j)));
        *reinterpret_cast<float4*>(&obase[(size_t)j * HW + rq * 4]) = v;
    }
}

extern "C" void kernel_launch(void* const* d_in, const int* in_sizes, int n_in,
                              void* d_out, int out_size)
{
    const float* feat  = (const float*)d_in[0];
    const float* times = (const float*)d_in[1];
    const float* w0 = (const float*)d_in[2];  const float* b0 = (const float*)d_in[3];
    const float* w1 = (const float*)d_in[4];  const float* b1 = (const float*)d_in[5];
    const float* w2 = (const float*)d_in[6];  const float* b2 = (const float*)d_in[7];
    const float* w3 = (const float*)d_in[8];  const float* b3 = (const float*)d_in[9];
    const float* w4 = (const float*)d_in[10]; const float* b4 = (const float*)d_in[11];
    const float* w5 = (const float*)d_in[12]; const float* b5 = (const float*)d_in[13];
    float* out = (float*)d_out;

    cudaFuncSetAttribute(liif_siren_kernel,
                         cudaFuncAttributeMaxDynamicSharedMemorySize,
                         (int)SM_TOTAL);

    const int total_rows = NTIMES * ROWS_PER_TIME;   // 368640
    const int blocks = total_rows / TILE_ROWS;       // 5760

    liif_siren_kernel<<<blocks, THREADS, SM_TOTAL>>>(
        feat, times,
        w0, b0, w1, b1, w2, b2, w3, b3, w4, b4, w5, b5,
        out);
}